// round 13
// baseline (speedup 1.0000x reference)
#include <cuda_runtime.h>

// Shapes: re, gt are (B=32, C=10, H=192, W=320) float32, contiguous.
#define NB     32
#define NC     10
#define HW2    30720                  // (192*320)/2 float2 groups per channel
#define N2     (NB*HW2)               // 983040 groups total
#define BLK    256
#define GRID   (N2/BLK)               // 3840 blocks, 1 group (2 px) per thread
#define NACC   6
#define EPSF   6e-8f

// [0]=nv [1]=num_pos [2]=focal_sum
// [3]=A (pos+height+const) [4]=B (len1+trig1) [5]=C (len2+trig2)
__device__ float g_part[NACC][GRID];
__device__ unsigned int g_count = 0;   // reset by last block each launch

__device__ __forceinline__ float sl1(float d) {
    float ad = fabsf(d);
    return ad < 1.0f ? 0.5f * d * d : ad - 0.5f;
}

__device__ __forceinline__ float c2(const float2& v, int j) {
    return j == 0 ? v.x : v.y;
}

__global__ void __launch_bounds__(BLK, 4)
loss_kernel(const float* __restrict__ re, const float* __restrict__ gt,
            float* __restrict__ out) {
    float a_nv = 0.f, a_np = 0.f, a_f = 0.f, a_A = 0.f, a_B = 0.f, a_C = 0.f;

    const float2* __restrict__ re2 = (const float2*)re;
    const float2* __restrict__ gt2 = (const float2*)gt;

    const int i   = blockIdx.x * BLK + threadIdx.x;   // group index, < N2
    const int b   = i / HW2;
    const int hw2 = i - b * HW2;
    const int bs  = b * (NC * HW2) + hw2;             // float2 idx of (b,0,hw)

    // ---- window 1: channel 0 ----
    const float2 G0 = gt2[bs];
    const float2 R0 = re2[bs];

    float mvf[2];
#pragma unroll
    for (int j = 0; j < 2; j++) {
        const float g = c2(G0, j);
        const float r = c2(R0, j);
        const bool  m0  = (g >= 0.0f);
        const bool  pos = (g >= 0.1f);                // FOCAL_THR, implies m0
        const float safe = fminf(fmaxf(r, 1e-6f), 1.0f - 1e-6f);
        const float larg = pos ? (safe + EPSF) : (1.0f + EPSF - safe);
        const float lg   = __logf(larg);              // larg > 0 always
        const float d0   = g - r;
        const float om   = 1.0f - g;
        const float om2  = om * om;
        float w = pos ? (d0 * d0) : (r * r * (om2 * om2));
        if (!m0) w = 0.0f;
        a_f -= w * lg;
        if (pos) a_np += 1.0f;
        mvf[j] = (g == 1.0f) ? 1.0f : 0.0f;
        a_nv += mvf[j];
    }

    if (mvf[0] + mvf[1] != 0.0f) {
        // ---- window 2: ALL 18 remaining loads batched (36 data regs) ----
        const float2 R1 = re2[bs + 1*HW2], G1 = gt2[bs + 1*HW2];
        const float2 R2 = re2[bs + 2*HW2], G2 = gt2[bs + 2*HW2];
        const float2 R3 = re2[bs + 3*HW2], G3 = gt2[bs + 3*HW2];
        const float2 R4 = re2[bs + 4*HW2], G4 = gt2[bs + 4*HW2];
        const float2 R5 = re2[bs + 5*HW2], G5 = gt2[bs + 5*HW2];
        const float2 R6 = re2[bs + 6*HW2], G6 = gt2[bs + 6*HW2];
        const float2 R7 = re2[bs + 7*HW2], G7 = gt2[bs + 7*HW2];
        const float2 R8 = re2[bs + 8*HW2], G8 = gt2[bs + 8*HW2];
        const float2 R9 = re2[bs + 9*HW2], G9 = gt2[bs + 9*HW2];

#pragma unroll
        for (int j = 0; j < 2; j++) {
            const float m = mvf[j];
            if (m == 0.0f) continue;

            // pos (0.5 = POS_W/2) + height (0.1 = LEN_W)
            a_A += m * (0.5f * (sl1(c2(R1,j) - c2(G1,j))
                              + sl1(c2(R2,j) - c2(G2,j)))
                      + 0.1f * sl1(c2(R9,j) - c2(G9,j)));

            // length straight/crossed (0.05 = LEN_W/2)
            const float r3 = c2(R3,j), g3 = c2(G3,j);
            const float r6 = c2(R6,j), g6 = c2(G6,j);
            a_B += m * 0.05f * (sl1(r3 - g3) + sl1(r6 - g6));
            a_C += m * 0.05f * (sl1(r3 - g6) + sl1(r6 - g3));

            // trig (0.5 = TRIG_W/2) + const (0.5 = CONST_W)
            const float r4 = c2(R4,j), g4 = c2(G4,j);
            const float r5 = c2(R5,j), g5 = c2(G5,j);
            const float r7 = c2(R7,j), g7 = c2(G7,j);
            const float r8 = c2(R8,j), g8 = c2(G8,j);
            const float d44 = r4 - g4, d77 = r7 - g7;
            const float d55 = r5 - g5, d88 = r8 - g8;
            a_B += m * 0.5f * (d44*d44 + d77*d77 + d55*d55 + d88*d88);
            const float d47 = r4 - g7, d74 = r7 - g4;
            const float d58 = r5 - g8, d85 = r8 - g5;
            a_C += m * 0.5f * (d47*d47 + d74*d74 + d58*d58 + d85*d85);
            const float c1 = 1.0f - r5*r5 - r4*r4;
            const float c2v = 1.0f - r8*r8 - r7*r7;
            a_A += m * 0.5f * (c1*c1 + c2v*c2v);
        }
    }

    // Block reduction: warp shuffle -> shared -> per-block partial slot.
    float acc[NACC] = {a_nv, a_np, a_f, a_A, a_B, a_C};
    __shared__ float sh[BLK/32][NACC];
    const int lane = threadIdx.x & 31;
    const int warp = threadIdx.x >> 5;
#pragma unroll
    for (int k = 0; k < NACC; k++) {
        float v = acc[k];
#pragma unroll
        for (int o = 16; o > 0; o >>= 1)
            v += __shfl_down_sync(0xffffffffu, v, o);
        if (lane == 0) sh[warp][k] = v;
    }
    __syncthreads();
    if (threadIdx.x < NACC) {
        float v = 0.0f;
#pragma unroll
        for (int w = 0; w < BLK/32; w++) v += sh[w][threadIdx.x];
        g_part[threadIdx.x][blockIdx.x] = v;
    }

    // Last-block-done: the final block to arrive reduces all partials.
    __shared__ bool is_last;
    __threadfence();
    __syncthreads();
    if (threadIdx.x == 0) {
        unsigned int old = atomicAdd(&g_count, 1u);
        is_last = (old == GRID - 1);
    }
    __syncthreads();
    if (!is_last) return;

    __threadfence();   // ensure we see every block's partials

    // 6 warps reduce the 6 accumulators over all 3840 block partials.
    __shared__ float tot[NACC];
    if (warp < NACC) {
        float v = 0.0f;
        for (int j = lane; j < GRID; j += 32) v += g_part[warp][j];
#pragma unroll
        for (int o = 16; o > 0; o >>= 1)
            v += __shfl_down_sync(0xffffffffu, v, o);
        if (lane == 0) tot[warp] = v;
    }
    __syncthreads();

    if (threadIdx.x == 0) {
        g_count = 0;   // reset for next graph replay

        const float nv      = tot[0];
        const float num_pos = tot[1];
        const float S       = tot[2];
        const float focal = (num_pos == 0.0f) ? S : S / num_pos;
        out[0] = focal + (tot[3] + fminf(tot[4], tot[5])) / nv;
    }
}

extern "C" void kernel_launch(void* const* d_in, const int* in_sizes, int n_in,
                              void* d_out, int out_size) {
    const float* re = (const float*)d_in[0];
    const float* gt = (const float*)d_in[1];
    float* out = (float*)d_out;

    loss_kernel<<<GRID, BLK>>>(re, gt, out);
}